// round 1
// baseline (speedup 1.0000x reference)
#include <cuda_runtime.h>
#include <math.h>

#define BATCH 4
#define SEQ   2048
#define DM    1024
#define ROWS  (BATCH * SEQ)   // 8192

#define BM 64
#define BN 64
#define BK 16

// Scratch (allocation-free rule: __device__ globals)
__device__ float g_q[(size_t)ROWS * DM];
__device__ float g_k[(size_t)ROWS * DM];
__device__ float g_v[(size_t)ROWS * DM];
__device__ float g_s[(size_t)BATCH * SEQ * SEQ];

// ---------------------------------------------------------------------------
// C[M,N] = A[M,K] * B[N,K]^T + bias   (NT GEMM, torch-style Linear)
// M=8192, N=1024, K=1024, all multiples of tile sizes -> no bounds checks.
// ---------------------------------------------------------------------------
__global__ __launch_bounds__(256) void gemm_nt_bias(
    const float* __restrict__ A, const float* __restrict__ Bm,
    const float* __restrict__ bias, float* __restrict__ C,
    int M, int N, int K)
{
    __shared__ float As[BM][BK + 1];
    __shared__ float Bs[BN][BK + 1];

    const int tid = threadIdx.x;
    const int tx = tid & 15;       // 0..15
    const int ty = tid >> 4;       // 0..15
    const int row0 = blockIdx.y * BM;
    const int col0 = blockIdx.x * BN;

    float acc[4][4] = {};

    for (int k0 = 0; k0 < K; k0 += BK) {
        // Load A tile: 64x16 floats = 1024 elems, 256 threads, one float4 each
        {
            int r  = tid >> 2;          // 0..63
            int c4 = (tid & 3) * 4;     // 0,4,8,12
            float4 av = *reinterpret_cast<const float4*>(&A[(size_t)(row0 + r) * K + k0 + c4]);
            As[r][c4 + 0] = av.x; As[r][c4 + 1] = av.y;
            As[r][c4 + 2] = av.z; As[r][c4 + 3] = av.w;
            float4 bv = *reinterpret_cast<const float4*>(&Bm[(size_t)(col0 + r) * K + k0 + c4]);
            Bs[r][c4 + 0] = bv.x; Bs[r][c4 + 1] = bv.y;
            Bs[r][c4 + 2] = bv.z; Bs[r][c4 + 3] = bv.w;
        }
        __syncthreads();

        #pragma unroll
        for (int kk = 0; kk < BK; ++kk) {
            float a[4], b[4];
            #pragma unroll
            for (int i = 0; i < 4; ++i) a[i] = As[ty * 4 + i][kk];
            #pragma unroll
            for (int j = 0; j < 4; ++j) b[j] = Bs[tx * 4 + j][kk];
            #pragma unroll
            for (int i = 0; i < 4; ++i)
                #pragma unroll
                for (int j = 0; j < 4; ++j)
                    acc[i][j] += a[i] * b[j];
        }
        __syncthreads();
    }

    #pragma unroll
    for (int i = 0; i < 4; ++i) {
        int r = row0 + ty * 4 + i;
        int c = col0 + tx * 4;
        float4 o;
        o.x = acc[i][0] + bias[c + 0];
        o.y = acc[i][1] + bias[c + 1];
        o.z = acc[i][2] + bias[c + 2];
        o.w = acc[i][3] + bias[c + 3];
        *reinterpret_cast<float4*>(&C[(size_t)r * N + c]) = o;
    }
}

// ---------------------------------------------------------------------------
// scores[b, i, j] = (Q[b,i,:] . K[b,j,:]) / sqrt(D), causal mask (j>i -> -inf)
// Blocks fully above the diagonal skip compute entirely.
// ---------------------------------------------------------------------------
__global__ __launch_bounds__(256) void scores_kernel(
    const float* __restrict__ Q, const float* __restrict__ Kmat,
    float* __restrict__ Sout)
{
    const int b = blockIdx.z;
    const float* A  = Q    + (size_t)b * SEQ * DM;
    const float* Bm = Kmat + (size_t)b * SEQ * DM;
    float* C = Sout + (size_t)b * SEQ * SEQ;

    const int tid = threadIdx.x;
    const int tx = tid & 15;
    const int ty = tid >> 4;
    const int row0 = blockIdx.y * BM;
    const int col0 = blockIdx.x * BN;

    if (col0 > row0) {
        // Entire tile above diagonal -> -inf (softmax turns into 0)
        #pragma unroll
        for (int i = 0; i < 4; ++i) {
            int r = row0 + ty * 4 + i;
            float4 o = make_float4(-INFINITY, -INFINITY, -INFINITY, -INFINITY);
            *reinterpret_cast<float4*>(&C[(size_t)r * SEQ + col0 + tx * 4]) = o;
        }
        return;
    }

    __shared__ float As[BM][BK + 1];
    __shared__ float Bs[BN][BK + 1];
    float acc[4][4] = {};

    for (int k0 = 0; k0 < DM; k0 += BK) {
        int r  = tid >> 2;
        int c4 = (tid & 3) * 4;
        float4 av = *reinterpret_cast<const float4*>(&A[(size_t)(row0 + r) * DM + k0 + c4]);
        As[r][c4 + 0] = av.x; As[r][c4 + 1] = av.y;
        As[r][c4 + 2] = av.z; As[r][c4 + 3] = av.w;
        float4 bv = *reinterpret_cast<const float4*>(&Bm[(size_t)(col0 + r) * DM + k0 + c4]);
        Bs[r][c4 + 0] = bv.x; Bs[r][c4 + 1] = bv.y;
        Bs[r][c4 + 2] = bv.z; Bs[r][c4 + 3] = bv.w;
        __syncthreads();

        #pragma unroll
        for (int kk = 0; kk < BK; ++kk) {
            float a[4], bb[4];
            #pragma unroll
            for (int i = 0; i < 4; ++i) a[i] = As[ty * 4 + i][kk];
            #pragma unroll
            for (int j = 0; j < 4; ++j) bb[j] = Bs[tx * 4 + j][kk];
            #pragma unroll
            for (int i = 0; i < 4; ++i)
                #pragma unroll
                for (int j = 0; j < 4; ++j)
                    acc[i][j] += a[i] * bb[j];
        }
        __syncthreads();
    }

    const float scale = 1.0f / 32.0f;   // 1/sqrt(1024)
    #pragma unroll
    for (int i = 0; i < 4; ++i) {
        int r = row0 + ty * 4 + i;
        int c = col0 + tx * 4;
        float4 o;
        o.x = (c + 0 <= r) ? acc[i][0] * scale : -INFINITY;
        o.y = (c + 1 <= r) ? acc[i][1] * scale : -INFINITY;
        o.z = (c + 2 <= r) ? acc[i][2] * scale : -INFINITY;
        o.w = (c + 3 <= r) ? acc[i][3] * scale : -INFINITY;
        *reinterpret_cast<float4*>(&C[(size_t)r * SEQ + c]) = o;
    }
}

// ---------------------------------------------------------------------------
// Row softmax over causal scores; writes probabilities in place, zeroes the
// masked tail so PV can read full tiles.
// ---------------------------------------------------------------------------
__global__ __launch_bounds__(256) void softmax_kernel(float* __restrict__ S)
{
    __shared__ float red[256];
    const int r  = blockIdx.x;            // 0..8191
    const int b  = r >> 11;
    const int qi = r & (SEQ - 1);
    float* row = S + ((size_t)b * SEQ + qi) * SEQ;
    const int L = qi + 1;
    const int tid = threadIdx.x;

    float m = -INFINITY;
    for (int j = tid; j < L; j += 256) m = fmaxf(m, row[j]);
    red[tid] = m; __syncthreads();
    #pragma unroll
    for (int s = 128; s > 0; s >>= 1) {
        if (tid < s) red[tid] = fmaxf(red[tid], red[tid + s]);
        __syncthreads();
    }
    m = red[0];
    __syncthreads();

    float acc = 0.0f;
    for (int j = tid; j < L; j += 256) {
        float e = expf(row[j] - m);
        row[j] = e;
        acc += e;
    }
    red[tid] = acc; __syncthreads();
    #pragma unroll
    for (int s = 128; s > 0; s >>= 1) {
        if (tid < s) red[tid] += red[tid + s];
        __syncthreads();
    }
    const float inv = 1.0f / red[0];

    for (int j = tid; j < L; j += 256) row[j] *= inv;
    for (int j = L + tid; j < SEQ; j += 256) row[j] = 0.0f;   // masked tail -> 0
}

// ---------------------------------------------------------------------------
// O[b] = P[b] (S x S) * V[b] (S x D)   (NN GEMM), K-loop limited by causality.
// ---------------------------------------------------------------------------
__global__ __launch_bounds__(256) void pv_kernel(
    const float* __restrict__ P, const float* __restrict__ V,
    float* __restrict__ O)
{
    const int b = blockIdx.z;
    const float* A  = P + (size_t)b * SEQ * SEQ;
    const float* Bv = V + (size_t)b * SEQ * DM;
    float* C = O + (size_t)b * SEQ * DM;

    const int tid = threadIdx.x;
    const int tx = tid & 15;
    const int ty = tid >> 4;
    const int row0 = blockIdx.y * BM;
    const int col0 = blockIdx.x * BN;

    __shared__ float As[BM][BK + 1];
    __shared__ float Bs[BK][BN];
    float acc[4][4] = {};

    const int kEnd = row0 + BM;   // causal: P[i,j]==0 for j>i, rows < row0+BM

    for (int k0 = 0; k0 < kEnd; k0 += BK) {
        {
            int r  = tid >> 2;
            int c4 = (tid & 3) * 4;
            float4 av = *reinterpret_cast<const float4*>(&A[(size_t)(row0 + r) * SEQ + k0 + c4]);
            As[r][c4 + 0] = av.x; As[r][c4 + 1] = av.y;
            As[r][c4 + 2] = av.z; As[r][c4 + 3] = av.w;
            // B tile: 16 x 64, one float4 per thread
            int br = tid >> 4;          // 0..15
            int bc = (tid & 15) * 4;    // 0..60
            float4 bv = *reinterpret_cast<const float4*>(&Bv[(size_t)(k0 + br) * DM + col0 + bc]);
            *reinterpret_cast<float4*>(&Bs[br][bc]) = bv;
        }
        __syncthreads();

        #pragma unroll
        for (int kk = 0; kk < BK; ++kk) {
            float a[4];
            #pragma unroll
            for (int i = 0; i < 4; ++i) a[i] = As[ty * 4 + i][kk];
            float4 bv = *reinterpret_cast<const float4*>(&Bs[kk][tx * 4]);
            float bb[4] = {bv.x, bv.y, bv.z, bv.w};
            #pragma unroll
            for (int i = 0; i < 4; ++i)
                #pragma unroll
                for (int j = 0; j < 4; ++j)
                    acc[i][j] += a[i] * bb[j];
        }
        __syncthreads();
    }

    #pragma unroll
    for (int i = 0; i < 4; ++i) {
        int r = row0 + ty * 4 + i;
        int c = col0 + tx * 4;
        float4 o = make_float4(acc[i][0], acc[i][1], acc[i][2], acc[i][3]);
        *reinterpret_cast<float4*>(&C[(size_t)r * DM + c]) = o;
    }
}

// ---------------------------------------------------------------------------
extern "C" void kernel_launch(void* const* d_in, const int* in_sizes, int n_in,
                              void* d_out, int out_size)
{
    (void)in_sizes; (void)n_in; (void)out_size;
    const float* x  = (const float*)d_in[0];
    const float* Wq = (const float*)d_in[1];
    const float* bq = (const float*)d_in[2];
    const float* Wk = (const float*)d_in[3];
    const float* bk = (const float*)d_in[4];
    const float* Wv = (const float*)d_in[5];
    const float* bv = (const float*)d_in[6];
    float* out = (float*)d_out;

    float *q, *k, *v, *s;
    cudaGetSymbolAddress((void**)&q, g_q);
    cudaGetSymbolAddress((void**)&k, g_k);
    cudaGetSymbolAddress((void**)&v, g_v);
    cudaGetSymbolAddress((void**)&s, g_s);

    dim3 blk(256);

    // QKV projections: [8192,1024] = x[8192,1024] @ W^T + b
    dim3 gProj(DM / BN, ROWS / BM);
    gemm_nt_bias<<<gProj, blk>>>(x, Wq, bq, q, ROWS, DM, DM);
    gemm_nt_bias<<<gProj, blk>>>(x, Wk, bk, k, ROWS, DM, DM);
    gemm_nt_bias<<<gProj, blk>>>(x, Wv, bv, v, ROWS, DM, DM);

    // Causal scores
    dim3 gScores(SEQ / BN, SEQ / BM, BATCH);
    scores_kernel<<<gScores, blk>>>(q, k, s);

    // Row softmax
    softmax_kernel<<<ROWS, blk>>>(s);

    // O = P V
    dim3 gPV(DM / BN, SEQ / BM, BATCH);
    pv_kernel<<<gPV, blk>>>(s, v, out);
}

// round 3
// speedup vs baseline: 2.5672x; 2.5672x over previous
#include <cuda_runtime.h>
#include <math.h>

#define BATCH 4
#define SEQ   2048
#define DM    1024
#define ROWS  (BATCH * SEQ)   // 8192

#define BM 128
#define BN 128
#define BK 16
#define LDA   20    // As row stride (uints): conflict-free for (m,k) frag reads
#define LDBNT 20    // Bs row stride for K-major (NT) B
#define LDBNN 136   // Bs row stride for N-major (NN) B

// Scratch (allocation-free rule: __device__ globals)
__device__ float g_q[(size_t)ROWS * DM];
__device__ float g_k[(size_t)ROWS * DM];
__device__ float g_v[(size_t)ROWS * DM];
__device__ float g_s[(size_t)BATCH * SEQ * SEQ];

__device__ __forceinline__ unsigned f2tf(float f) {
    unsigned u;
    asm("cvt.rna.tf32.f32 %0, %1;" : "=r"(u) : "f"(f));
    return u;
}

__device__ __forceinline__ void mma8(float c[4], const unsigned a[4], const unsigned b[2]) {
    asm volatile(
        "mma.sync.aligned.m16n8k8.row.col.f32.tf32.tf32.f32 "
        "{%0,%1,%2,%3},{%4,%5,%6,%7},{%8,%9},{%0,%1,%2,%3};"
        : "+f"(c[0]), "+f"(c[1]), "+f"(c[2]), "+f"(c[3])
        : "r"(a[0]), "r"(a[1]), "r"(a[2]), "r"(a[3]), "r"(b[0]), "r"(b[1]));
}

// ---------------------------------------------------------------------------
// Unified tf32 tensor-core GEMM.
// MODE 0: C[M,N] = A[M,K] B[N,K]^T + bias          (QKV projections)
// MODE 1: C[b]   = (A[b] B[b]^T) * 1/sqrt(D)        (scores; skip blocks above diag)
// MODE 2: C[b]   = A[b][S,S] B[b][S,D]              (PV; K-loop limited by causality)
// ---------------------------------------------------------------------------
template<int MODE>
__global__ __launch_bounds__(256) void mm_tf32(
    const float* __restrict__ Ag, const float* __restrict__ Bg,
    const float* __restrict__ bias, float* __restrict__ Cg)
{
    const int row0 = blockIdx.y * BM;
    const int col0 = blockIdx.x * BN;
    const float* A = Ag;
    const float* B = Bg;
    float* C = Cg;
    if (MODE == 1) {
        if (col0 > row0) return;   // fully masked tile: never read downstream
        size_t off = (size_t)blockIdx.z * SEQ * DM;
        A += off; B += off;
        C += (size_t)blockIdx.z * SEQ * SEQ;
    }
    if (MODE == 2) {
        A += (size_t)blockIdx.z * SEQ * SEQ;
        B += (size_t)blockIdx.z * SEQ * DM;
        C += (size_t)blockIdx.z * SEQ * DM;
    }
    const int ldA  = (MODE == 2) ? SEQ : DM;
    const int ldC  = (MODE == 1) ? SEQ : DM;
    const int kEnd = (MODE == 2) ? (row0 + BM) : DM;   // causal: P zero beyond row0+BM

    __shared__ unsigned As[2][BM * LDA];
    __shared__ unsigned Bs[2][BN * LDBNT];   // BN*LDBNT(2560) >= BK*LDBNN(2176)

    const int tid = threadIdx.x;
    const int ar = tid >> 1, ac = (tid & 1) * 8;                       // A tile 128x16
    const int br = (MODE == 2) ? (tid >> 4) : ar;                      // B tile 16x128 (NN)
    const int bc = (MODE == 2) ? ((tid & 15) * 8) : ac;                //   or 128x16 (NT)

    float areg[8], breg[8];

    auto ldg = [&](int k0) {
        const float4* pa = (const float4*)(A + (size_t)(row0 + ar) * ldA + k0 + ac);
        float4 a0 = pa[0], a1 = pa[1];
        areg[0] = a0.x; areg[1] = a0.y; areg[2] = a0.z; areg[3] = a0.w;
        areg[4] = a1.x; areg[5] = a1.y; areg[6] = a1.z; areg[7] = a1.w;
        const float4* pb = (MODE == 2)
            ? (const float4*)(B + (size_t)(k0 + br) * DM + col0 + bc)
            : (const float4*)(B + (size_t)(col0 + br) * DM + k0 + bc);
        float4 b0 = pb[0], b1 = pb[1];
        breg[0] = b0.x; breg[1] = b0.y; breg[2] = b0.z; breg[3] = b0.w;
        breg[4] = b1.x; breg[5] = b1.y; breg[6] = b1.z; breg[7] = b1.w;
    };
    auto sts = [&](int buf) {
        unsigned* da = &As[buf][ar * LDA + ac];
        #pragma unroll
        for (int i = 0; i < 8; ++i) da[i] = f2tf(areg[i]);
        unsigned* db = (MODE == 2) ? &Bs[buf][br * LDBNN + bc]
                                   : &Bs[buf][br * LDBNT + bc];
        #pragma unroll
        for (int i = 0; i < 8; ++i) db[i] = f2tf(breg[i]);
    };

    const int lane = tid & 31;
    const int wm = (tid >> 7) * 64;          // warp row origin (2 warp-rows)
    const int wn = ((tid >> 5) & 3) * 32;    // warp col origin (4 warp-cols)
    const int lq = lane >> 2, lr = lane & 3;

    float acc[4][4][4] = {};

    ldg(0);
    sts(0);
    __syncthreads();

    const int nIter = kEnd / BK;
    for (int it = 0; it < nIter; ++it) {
        const int buf = it & 1;
        if (it + 1 < nIter) ldg((it + 1) * BK);

        #pragma unroll
        for (int ks = 0; ks < 2; ++ks) {
            const int kk = ks * 8;
            unsigned af[4][4], bf[4][2];
            #pragma unroll
            for (int i = 0; i < 4; ++i) {
                const int m = wm + i * 16;
                af[i][0] = As[buf][(m + lq) * LDA + kk + lr];
                af[i][1] = As[buf][(m + 8 + lq) * LDA + kk + lr];
                af[i][2] = As[buf][(m + lq) * LDA + kk + 4 + lr];
                af[i][3] = As[buf][(m + 8 + lq) * LDA + kk + 4 + lr];
            }
            #pragma unroll
            for (int j = 0; j < 4; ++j) {
                const int n = wn + j * 8;
                if (MODE == 2) {
                    bf[j][0] = Bs[buf][(kk + lr) * LDBNN + n + lq];
                    bf[j][1] = Bs[buf][(kk + 4 + lr) * LDBNN + n + lq];
                } else {
                    bf[j][0] = Bs[buf][(n + lq) * LDBNT + kk + lr];
                    bf[j][1] = Bs[buf][(n + lq) * LDBNT + kk + 4 + lr];
                }
            }
            #pragma unroll
            for (int i = 0; i < 4; ++i)
                #pragma unroll
                for (int j = 0; j < 4; ++j)
                    mma8(acc[i][j], af[i], bf[j]);
        }
        if (it + 1 < nIter) sts(buf ^ 1);
        __syncthreads();
    }

    // Epilogue
    #pragma unroll
    for (int i = 0; i < 4; ++i) {
        const int r = row0 + wm + i * 16 + lq;
        #pragma unroll
        for (int j = 0; j < 4; ++j) {
            const int c = col0 + wn + j * 8 + 2 * lr;
            float2 v0, v1;
            v0.x = acc[i][j][0]; v0.y = acc[i][j][1];
            v1.x = acc[i][j][2]; v1.y = acc[i][j][3];
            if (MODE == 0) {
                const float b0 = bias[c], b1 = bias[c + 1];
                v0.x += b0; v0.y += b1; v1.x += b0; v1.y += b1;
            }
            if (MODE == 1) {
                const float scale = 1.0f / 32.0f;   // 1/sqrt(1024)
                v0.x *= scale; v0.y *= scale; v1.x *= scale; v1.y *= scale;
            }
            *(float2*)&C[(size_t)r * ldC + c] = v0;
            *(float2*)&C[(size_t)(r + 8) * ldC + c] = v1;
        }
    }
}

// ---------------------------------------------------------------------------
// Row softmax over causal scores (reads only j <= qi; zeroes the masked tail).
// ---------------------------------------------------------------------------
__device__ __forceinline__ float warpMax(float v) {
    #pragma unroll
    for (int o = 16; o; o >>= 1) v = fmaxf(v, __shfl_xor_sync(0xffffffffu, v, o));
    return v;
}
__device__ __forceinline__ float warpSum(float v) {
    #pragma unroll
    for (int o = 16; o; o >>= 1) v += __shfl_xor_sync(0xffffffffu, v, o);
    return v;
}

__global__ __launch_bounds__(256) void softmax_kernel(float* __restrict__ S)
{
    __shared__ float red[8];
    const int r = blockIdx.x;               // 0..8191 (batch-major rows)
    const int qi = r & (SEQ - 1);
    float* row = S + (size_t)r * SEQ;
    const int L = qi + 1;
    const int L4 = L >> 2;                  // full float4 count
    float4* row4 = (float4*)row;
    const int tid = threadIdx.x;
    const int wid = tid >> 5, lane = tid & 31;

    float m = -INFINITY;
    for (int j = tid; j < L4; j += 256) {
        float4 v = row4[j];
        m = fmaxf(m, fmaxf(fmaxf(v.x, v.y), fmaxf(v.z, v.w)));
    }
    for (int j = L4 * 4 + tid; j < L; j += 256) m = fmaxf(m, row[j]);
    m = warpMax(m);
    if (lane == 0) red[wid] = m;
    __syncthreads();
    // FIX (R2 bug): read each warp partial exactly ONCE in the final reduce.
    m = (lane < 8) ? red[lane] : -INFINITY;
    m = warpMax(m);
    __syncthreads();

    float s = 0.0f;
    for (int j = tid; j < L4; j += 256) {
        float4 v = row4[j];
        v.x = __expf(v.x - m); v.y = __expf(v.y - m);
        v.z = __expf(v.z - m); v.w = __expf(v.w - m);
        s += v.x + v.y + v.z + v.w;
        row4[j] = v;
    }
    for (int j = L4 * 4 + tid; j < L; j += 256) {
        float e = __expf(row[j] - m);
        row[j] = e;
        s += e;
    }
    s = warpSum(s);
    if (lane == 0) red[wid] = s;
    __syncthreads();
    // FIX (R2 bug): previously red[lane & 7] made each warp-sum count 4x,
    // scaling the softmax denominator by 4 (observed rel_err = 0.75).
    s = (lane < 8) ? red[lane] : 0.0f;
    s = warpSum(s);
    const float inv = 1.0f / s;

    for (int j = tid; j < L4; j += 256) {
        float4 v = row4[j];
        v.x *= inv; v.y *= inv; v.z *= inv; v.w *= inv;
        row4[j] = v;
    }
    for (int j = L4 * 4 + tid; j < L; j += 256) row[j] *= inv;
    // Zero the masked tail so PV can consume full tiles.
    for (int j = L + tid; j < SEQ; j += 256) row[j] = 0.0f;
}

// ---------------------------------------------------------------------------
extern "C" void kernel_launch(void* const* d_in, const int* in_sizes, int n_in,
                              void* d_out, int out_size)
{
    (void)in_sizes; (void)n_in; (void)out_size;
    const float* x  = (const float*)d_in[0];
    const float* Wq = (const float*)d_in[1];
    const float* bq = (const float*)d_in[2];
    const float* Wk = (const float*)d_in[3];
    const float* bk = (const float*)d_in[4];
    const float* Wv = (const float*)d_in[5];
    const float* bv = (const float*)d_in[6];
    float* out = (float*)d_out;

    float *q, *k, *v, *s;
    cudaGetSymbolAddress((void**)&q, g_q);
    cudaGetSymbolAddress((void**)&k, g_k);
    cudaGetSymbolAddress((void**)&v, g_v);
    cudaGetSymbolAddress((void**)&s, g_s);

    dim3 blk(256);

    // QKV projections: [8192,1024] = x @ W^T + b
    dim3 gProj(DM / BN, ROWS / BM);
    mm_tf32<0><<<gProj, blk>>>(x, Wq, bq, q);
    mm_tf32<0><<<gProj, blk>>>(x, Wk, bk, k);
    mm_tf32<0><<<gProj, blk>>>(x, Wv, bv, v);

    // Causal scores (above-diagonal tiles skipped, never written)
    dim3 gScores(SEQ / BN, SEQ / BM, BATCH);
    mm_tf32<1><<<gScores, blk>>>(q, k, nullptr, s);

    // Row softmax
    softmax_kernel<<<ROWS, blk>>>(s);

    // O = P V
    dim3 gPV(DM / BN, SEQ / BM, BATCH);
    mm_tf32<2><<<gPV, blk>>>(s, v, nullptr, out);
}

// round 5
// speedup vs baseline: 3.4625x; 1.3488x over previous
#include <cuda_runtime.h>
#include <math.h>
#include <float.h>

#define BATCH 4
#define SEQ   2048
#define DM    1024
#define ROWS  (BATCH * SEQ)   // 8192

#define BM 128
#define BN 128
#define BK 16
#define LDA   20     // As row stride (uints): conflict-free fragment reads
#define LDBNT 20     // Bs row stride, K-major (NT) B
#define LDBNN 136    // Bs row stride, N-major (NN) B
#define STAGES 3
#define STAGE_U 5120           // uints per stage: As 2560 + Bs 2560
#define SMEM_BYTES (STAGES * STAGE_U * 4)   // 61440

// Scratch (allocation-free rule: __device__ globals)
__device__ float g_q[(size_t)ROWS * DM];
__device__ float g_k[(size_t)ROWS * DM];
__device__ float g_v[(size_t)ROWS * DM];
__device__ float g_s[(size_t)BATCH * SEQ * SEQ];
__device__ float g_xt[(size_t)ROWS * DM];   // tf32-rounded x
__device__ float g_wq[(size_t)DM * DM];
__device__ float g_wk[(size_t)DM * DM];
__device__ float g_wv[(size_t)DM * DM];

__device__ __forceinline__ unsigned f2tf(float f) {
    unsigned u;
    asm("cvt.rna.tf32.f32 %0, %1;" : "=r"(u) : "f"(f));
    return u;
}
__device__ __forceinline__ float rtf(float f) { return __uint_as_float(f2tf(f)); }

__device__ __forceinline__ void mma8(float c[4], const unsigned a[4], const unsigned b[2]) {
    asm volatile(
        "mma.sync.aligned.m16n8k8.row.col.f32.tf32.tf32.f32 "
        "{%0,%1,%2,%3},{%4,%5,%6,%7},{%8,%9},{%0,%1,%2,%3};"
        : "+f"(c[0]), "+f"(c[1]), "+f"(c[2]), "+f"(c[3])
        : "r"(a[0]), "r"(a[1]), "r"(a[2]), "r"(a[3]), "r"(b[0]), "r"(b[1]));
}

__device__ __forceinline__ void cp16(unsigned smem_u32, const float* gptr) {
    asm volatile("cp.async.cg.shared.global [%0], [%1], 16;\n"
                 :: "r"(smem_u32), "l"(gptr));
}
__device__ __forceinline__ void cp_commit() {
    asm volatile("cp.async.commit_group;\n");
}
template<int N>
__device__ __forceinline__ void cp_wait() {
    asm volatile("cp.async.wait_group %0;\n" :: "n"(N));
}

// ---------------------------------------------------------------------------
// Elementwise tf32 pre-round (RNA) of GEMM operands.
// ---------------------------------------------------------------------------
__global__ void cvt_tf32(const float* __restrict__ in, float* __restrict__ out, int n4)
{
    int i = blockIdx.x * blockDim.x + threadIdx.x;
    if (i >= n4) return;
    float4 v = ((const float4*)in)[i];
    v.x = rtf(v.x); v.y = rtf(v.y); v.z = rtf(v.z); v.w = rtf(v.w);
    ((float4*)out)[i] = v;
}

// ---------------------------------------------------------------------------
// Unified tf32 tensor-core GEMM, cp.async 3-stage pipeline, zero-cvt mainloop.
// MODE 0: C = A B^T + bias, output tf32-rounded      (QKV projections)
// MODE 1: C[b] = (A[b] B[b]^T)/sqrt(D), skip above-diag tiles  (scores)
// MODE 2: C[b] = A[b][S,S] B[b][S,D], K limited by causality   (PV)
// All operands are pre-rounded to tf32-representable fp32.
// ---------------------------------------------------------------------------
template<int MODE>
__global__ __launch_bounds__(256, 2) void mm_tf32(
    const float* __restrict__ Ag, const float* __restrict__ Bg,
    const float* __restrict__ bias, float* __restrict__ Cg)
{
    const int row0 = blockIdx.y * BM;
    const int col0 = blockIdx.x * BN;
    const float* A = Ag;
    const float* B = Bg;
    float* C = Cg;
    if (MODE == 1) {
        if (col0 > row0) return;
        size_t off = (size_t)blockIdx.z * SEQ * DM;
        A += off; B += off;
        C += (size_t)blockIdx.z * SEQ * SEQ;
    }
    if (MODE == 2) {
        A += (size_t)blockIdx.z * SEQ * SEQ;
        B += (size_t)blockIdx.z * SEQ * DM;
        C += (size_t)blockIdx.z * SEQ * DM;
    }
    const int ldA  = (MODE == 2) ? SEQ : DM;
    const int ldC  = (MODE == 1) ? SEQ : DM;
    const int kEnd = (MODE == 2) ? (row0 + BM) : DM;

    extern __shared__ __align__(16) unsigned smem[];

    const int tid = threadIdx.x;
    // cp.async per-thread mapping (2 x 16B chunks for A, 2 for B)
    const int ar0 = tid >> 2;            // A rows: ar0, ar0+64
    const int ac0 = (tid & 3) * 4;
    const int br0 = (MODE == 2) ? (tid >> 5) : ar0;       // NN: rows br0, br0+8
    const int bc0 = (MODE == 2) ? ((tid & 31) * 4) : ac0;

    const unsigned smem_base = (unsigned)__cvta_generic_to_shared(smem);

    auto issue = [&](int it) {
        const int k0 = it * BK;
        const unsigned sa = smem_base + ((it % STAGES) * STAGE_U) * 4;
        const unsigned sb = sa + 2560 * 4;
        cp16(sa + (ar0 * LDA + ac0) * 4,        A + (size_t)(row0 + ar0) * ldA + k0 + ac0);
        cp16(sa + ((ar0 + 64) * LDA + ac0) * 4, A + (size_t)(row0 + ar0 + 64) * ldA + k0 + ac0);
        if (MODE == 2) {
            cp16(sb + (br0 * LDBNN + bc0) * 4,       B + (size_t)(k0 + br0) * DM + col0 + bc0);
            cp16(sb + ((br0 + 8) * LDBNN + bc0) * 4, B + (size_t)(k0 + br0 + 8) * DM + col0 + bc0);
        } else {
            cp16(sb + (br0 * LDBNT + bc0) * 4,        B + (size_t)(col0 + br0) * DM + k0 + bc0);
            cp16(sb + ((br0 + 64) * LDBNT + bc0) * 4, B + (size_t)(col0 + br0 + 64) * DM + k0 + bc0);
        }
    };

    const int lane = tid & 31;
    const int wm = (tid >> 7) * 64;
    const int wn = ((tid >> 5) & 3) * 32;
    const int lq = lane >> 2, lr = lane & 3;

    float acc[4][4][4] = {};

    const int nIter = kEnd / BK;

    #pragma unroll
    for (int s = 0; s < STAGES - 1; ++s) {
        if (s < nIter) issue(s);
        cp_commit();
    }

    for (int it = 0; it < nIter; ++it) {
        cp_wait<STAGES - 2>();
        __syncthreads();

        if (it + STAGES - 1 < nIter) issue(it + STAGES - 1);
        cp_commit();

        const unsigned* As = smem + (it % STAGES) * STAGE_U;
        const unsigned* Bs = As + 2560;

        #pragma unroll
        for (int ks = 0; ks < 2; ++ks) {
            const int kk = ks * 8;
            unsigned af[4][4], bf[4][2];
            #pragma unroll
            for (int i = 0; i < 4; ++i) {
                const int m = wm + i * 16;
                af[i][0] = As[(m + lq) * LDA + kk + lr];
                af[i][1] = As[(m + 8 + lq) * LDA + kk + lr];
                af[i][2] = As[(m + lq) * LDA + kk + 4 + lr];
                af[i][3] = As[(m + 8 + lq) * LDA + kk + 4 + lr];
            }
            #pragma unroll
            for (int j = 0; j < 4; ++j) {
                const int n = wn + j * 8;
                if (MODE == 2) {
                    bf[j][0] = Bs[(kk + lr) * LDBNN + n + lq];
                    bf[j][1] = Bs[(kk + 4 + lr) * LDBNN + n + lq];
                } else {
                    bf[j][0] = Bs[(n + lq) * LDBNT + kk + lr];
                    bf[j][1] = Bs[(n + lq) * LDBNT + kk + 4 + lr];
                }
            }
            #pragma unroll
            for (int i = 0; i < 4; ++i)
                #pragma unroll
                for (int j = 0; j < 4; ++j)
                    mma8(acc[i][j], af[i], bf[j]);
        }
    }

    // Epilogue
    #pragma unroll
    for (int i = 0; i < 4; ++i) {
        const int r = row0 + wm + i * 16 + lq;
        #pragma unroll
        for (int j = 0; j < 4; ++j) {
            const int c = col0 + wn + j * 8 + 2 * lr;
            float2 v0, v1;
            v0.x = acc[i][j][0]; v0.y = acc[i][j][1];
            v1.x = acc[i][j][2]; v1.y = acc[i][j][3];
            if (MODE == 0) {
                const float b0 = bias[c], b1 = bias[c + 1];
                // store tf32-rounded q/k/v so downstream GEMMs skip cvt
                v0.x = rtf(v0.x + b0); v0.y = rtf(v0.y + b1);
                v1.x = rtf(v1.x + b0); v1.y = rtf(v1.y + b1);
            }
            if (MODE == 1) {
                const float scale = 1.0f / 32.0f;   // 1/sqrt(1024)
                v0.x *= scale; v0.y *= scale; v1.x *= scale; v1.y *= scale;
            }
            *(float2*)&C[(size_t)r * ldC + c] = v0;
            *(float2*)&C[(size_t)(r + 8) * ldC + c] = v1;
        }
    }
}

// ---------------------------------------------------------------------------
// Online softmax. NaN fix (R4 bug): running max starts at -FLT_MAX, not -inf.
// With -inf, lanes owning no elements computed 0 * expf(-inf - -inf) = NaN in
// the shuffle combine. -FLT_MAX keeps (m - nm) finite on every path.
// ---------------------------------------------------------------------------
__global__ __launch_bounds__(256) void softmax_kernel(float* __restrict__ S)
{
    __shared__ float redm[8], reds[8];
    const int r = blockIdx.x;
    const int qi = r & (SEQ - 1);
    float* row = S + (size_t)r * SEQ;
    const int L = qi + 1;
    const int L4 = L >> 2;
    float4* row4 = (float4*)row;
    const int tid = threadIdx.x;
    const int wid = tid >> 5, lane = tid & 31;

    float m = -FLT_MAX, s = 0.0f;
    for (int j = tid; j < L4; j += 256) {
        float4 v = row4[j];
        float cm = fmaxf(fmaxf(v.x, v.y), fmaxf(v.z, v.w));
        float nm = fmaxf(m, cm);
        s = s * __expf(m - nm)
          + __expf(v.x - nm) + __expf(v.y - nm) + __expf(v.z - nm) + __expf(v.w - nm);
        m = nm;
    }
    for (int j = L4 * 4 + tid; j < L; j += 256) {
        float v = row[j];
        float nm = fmaxf(m, v);
        s = s * __expf(m - nm) + __expf(v - nm);
        m = nm;
    }
    // combine (m, s) across warp — all terms finite now
    #pragma unroll
    for (int o = 16; o; o >>= 1) {
        float m2 = __shfl_xor_sync(0xffffffffu, m, o);
        float s2 = __shfl_xor_sync(0xffffffffu, s, o);
        float nm = fmaxf(m, m2);
        s = s * __expf(m - nm) + s2 * __expf(m2 - nm);
        m = nm;
    }
    if (lane == 0) { redm[wid] = m; reds[wid] = s; }
    __syncthreads();
    float M = -FLT_MAX;
    #pragma unroll
    for (int w = 0; w < 8; ++w) M = fmaxf(M, redm[w]);
    float Stot = 0.0f;
    #pragma unroll
    for (int w = 0; w < 8; ++w) Stot += reds[w] * __expf(redm[w] - M);
    const float inv = 1.0f / Stot;

    for (int j = tid; j < L4; j += 256) {
        float4 v = row4[j];
        v.x = rtf(__expf(v.x - M) * inv);
        v.y = rtf(__expf(v.y - M) * inv);
        v.z = rtf(__expf(v.z - M) * inv);
        v.w = rtf(__expf(v.w - M) * inv);
        row4[j] = v;
    }
    for (int j = L4 * 4 + tid; j < L; j += 256)
        row[j] = rtf(__expf(row[j] - M) * inv);
    for (int j = L + tid; j < SEQ; j += 256) row[j] = 0.0f;
}

// ---------------------------------------------------------------------------
extern "C" void kernel_launch(void* const* d_in, const int* in_sizes, int n_in,
                              void* d_out, int out_size)
{
    (void)in_sizes; (void)n_in; (void)out_size;
    const float* x  = (const float*)d_in[0];
    const float* Wq = (const float*)d_in[1];
    const float* bq = (const float*)d_in[2];
    const float* Wk = (const float*)d_in[3];
    const float* bk = (const float*)d_in[4];
    const float* Wv = (const float*)d_in[5];
    const float* bv = (const float*)d_in[6];
    float* out = (float*)d_out;

    float *q, *k, *v, *s, *xt, *wq, *wk, *wv;
    cudaGetSymbolAddress((void**)&q,  g_q);
    cudaGetSymbolAddress((void**)&k,  g_k);
    cudaGetSymbolAddress((void**)&v,  g_v);
    cudaGetSymbolAddress((void**)&s,  g_s);
    cudaGetSymbolAddress((void**)&xt, g_xt);
    cudaGetSymbolAddress((void**)&wq, g_wq);
    cudaGetSymbolAddress((void**)&wk, g_wk);
    cudaGetSymbolAddress((void**)&wv, g_wv);

    // Idempotent, capture-safe; called unconditionally (no static state).
    cudaFuncSetAttribute(mm_tf32<0>, cudaFuncAttributeMaxDynamicSharedMemorySize, SMEM_BYTES);
    cudaFuncSetAttribute(mm_tf32<1>, cudaFuncAttributeMaxDynamicSharedMemorySize, SMEM_BYTES);
    cudaFuncSetAttribute(mm_tf32<2>, cudaFuncAttributeMaxDynamicSharedMemorySize, SMEM_BYTES);

    dim3 blk(256);

    // tf32 pre-round of GEMM operands
    const int nX4 = ROWS * DM / 4, nW4 = DM * DM / 4;
    cvt_tf32<<<(nX4 + 255) / 256, blk>>>(x,  xt, nX4);
    cvt_tf32<<<(nW4 + 255) / 256, blk>>>(Wq, wq, nW4);
    cvt_tf32<<<(nW4 + 255) / 256, blk>>>(Wk, wk, nW4);
    cvt_tf32<<<(nW4 + 255) / 256, blk>>>(Wv, wv, nW4);

    // QKV projections
    dim3 gProj(DM / BN, ROWS / BM);
    mm_tf32<0><<<gProj, blk, SMEM_BYTES>>>(xt, wq, bq, q);
    mm_tf32<0><<<gProj, blk, SMEM_BYTES>>>(xt, wk, bk, k);
    mm_tf32<0><<<gProj, blk, SMEM_BYTES>>>(xt, wv, bv, v);

    // Causal scores
    dim3 gScores(SEQ / BN, SEQ / BM, BATCH);
    mm_tf32<1><<<gScores, blk, SMEM_BYTES>>>(q, k, nullptr, s);

    // Row softmax (writes tf32-rounded probs)
    softmax_kernel<<<ROWS, blk>>>(s);

    // O = P V
    dim3 gPV(DM / BN, SEQ / BM, BATCH);
    mm_tf32<2><<<gPV, blk, SMEM_BYTES>>>(s, v, nullptr, out);
}

// round 7
// speedup vs baseline: 6.1833x; 1.7858x over previous
#include <cuda_runtime.h>
#include <cuda_fp16.h>
#include <math.h>
#include <float.h>
#include <stdint.h>

#define BATCH 4
#define SEQ   2048
#define DM    1024
#define ROWS  (BATCH * SEQ)   // 8192

#define BM 128
#define BN 128
#define BK 32                 // halves per K-slice
#define LDH 40                // halves per smem row (padded; 20 words -> conflict-free)
#define STAGES 3
#define MAT_BYTES (128 * LDH * 2)            // 10240 per matrix tile
#define STG_BYTES (2 * MAT_BYTES)            // 20480
#define SMEM_BYTES (STAGES * STG_BYTES)      // 61440

// Scratch (allocation-free rule: __device__ globals)
__device__ __half g_xh[(size_t)ROWS * DM];
__device__ __half g_wq[(size_t)DM * DM];
__device__ __half g_wk[(size_t)DM * DM];
__device__ __half g_wv[(size_t)DM * DM];
__device__ __half g_qh[(size_t)ROWS * DM];
__device__ __half g_kh[(size_t)ROWS * DM];
__device__ __half g_vt[(size_t)BATCH * DM * SEQ];  // V transposed per batch
__device__ float  g_s [(size_t)BATCH * SEQ * SEQ]; // fp32 scores
__device__ __half g_p [(size_t)BATCH * SEQ * SEQ]; // fp16 probs

__device__ __forceinline__ void mma16(float c[4], const unsigned a[4], const unsigned b[2]) {
    asm volatile(
        "mma.sync.aligned.m16n8k16.row.col.f32.f16.f16.f32 "
        "{%0,%1,%2,%3},{%4,%5,%6,%7},{%8,%9},{%0,%1,%2,%3};"
        : "+f"(c[0]), "+f"(c[1]), "+f"(c[2]), "+f"(c[3])
        : "r"(a[0]), "r"(a[1]), "r"(a[2]), "r"(a[3]), "r"(b[0]), "r"(b[1]));
}

__device__ __forceinline__ void cp16(unsigned smem_u32, const void* gptr) {
    asm volatile("cp.async.cg.shared.global [%0], [%1], 16;\n" :: "r"(smem_u32), "l"(gptr));
}
__device__ __forceinline__ void cp_commit() { asm volatile("cp.async.commit_group;\n"); }
template<int N>
__device__ __forceinline__ void cp_wait() { asm volatile("cp.async.wait_group %0;\n" :: "n"(N)); }

// ---------------------------------------------------------------------------
// fp32 -> fp16 conversion (RN)
// ---------------------------------------------------------------------------
__global__ void cvt_f2h(const float* __restrict__ in, __half* __restrict__ out, int n4)
{
    int i = blockIdx.x * blockDim.x + threadIdx.x;
    if (i >= n4) return;
    float4 v = ((const float4*)in)[i];
    __half2 h0 = __float22half2_rn(make_float2(v.x, v.y));
    __half2 h1 = __float22half2_rn(make_float2(v.z, v.w));
    ((__half2*)out)[2 * i]     = h0;
    ((__half2*)out)[2 * i + 1] = h1;
}

// ---------------------------------------------------------------------------
// fp16 m16n8k16 GEMM, 128x128 tile, cp.async 3-stage. All modes NT K-major.
// MODE 0: Ch = (A W^T + bias)           half out      (Q/K projections)
// MODE 3: Vt = (A W^T + bias)^T         half out      (V projection, transposed)
// MODE 1: S[b] = (Q K^T)/32             fp32 out, skip above-diag tiles
// MODE 2: O[b] = P Vt^T                 fp32 out, K limited by causality
// ---------------------------------------------------------------------------
template<int MODE>
__global__ __launch_bounds__(256, 2) void mm_h(
    const __half* __restrict__ Ag, const __half* __restrict__ Bg,
    const float* __restrict__ bias, void* __restrict__ Cg)
{
    const int row0 = blockIdx.y * BM;
    const int col0 = blockIdx.x * BN;
    const __half* A = Ag;
    const __half* B = Bg;
    int ldA = DM, ldB = DM;
    if (MODE == 1) {
        if (col0 > row0) return;     // fully masked tile, never read downstream
        size_t off = (size_t)blockIdx.z * SEQ * DM;
        A += off; B += off;
    }
    if (MODE == 2) {
        A += (size_t)blockIdx.z * SEQ * SEQ;
        B += (size_t)blockIdx.z * DM * SEQ;
        ldA = SEQ; ldB = SEQ;
    }
    const int kEnd  = (MODE == 2) ? (row0 + BM) : DM;
    const int nIter = kEnd / BK;

    extern __shared__ __align__(16) __half smem_h[];
    const unsigned smem_base = (unsigned)__cvta_generic_to_shared(smem_h);

    const int tid = threadIdx.x;
    // cp.async mapping: each tile 128 rows x 32 halves = 512 x 16B chunks
    // A: chunks t*256+tid, t=0..1 ; B: same
    auto issue = [&](int it) {
        const int k0 = it * BK;
        const unsigned sa = smem_base + (it % STAGES) * STG_BYTES;
        const unsigned sb = sa + MAT_BYTES;
        #pragma unroll
        for (int t = 0; t < 2; ++t) {
            int cid = tid + t * 256;
            int r = cid >> 2, c8 = (cid & 3) * 8;
            cp16(sa + (r * LDH + c8) * 2, A + (size_t)(row0 + r) * ldA + k0 + c8);
        }
        #pragma unroll
        for (int t = 0; t < 2; ++t) {
            int cid = tid + t * 256;
            int r = cid >> 2, c8 = (cid & 3) * 8;
            cp16(sb + (r * LDH + c8) * 2, B + (size_t)(col0 + r) * ldB + k0 + c8);
        }
    };

    const int lane = tid & 31;
    const int wm = (tid >> 7) * 64;          // warp rows
    const int wn = ((tid >> 5) & 3) * 32;    // warp cols
    const int lq = lane >> 2, lr = lane & 3;

    float acc[4][4][4] = {};

    #pragma unroll
    for (int s = 0; s < STAGES - 1; ++s) {
        if (s < nIter) issue(s);
        cp_commit();
    }

    for (int it = 0; it < nIter; ++it) {
        cp_wait<STAGES - 2>();
        __syncthreads();

        if (it + STAGES - 1 < nIter) issue(it + STAGES - 1);
        cp_commit();

        const unsigned* As = (const unsigned*)(smem_h + (size_t)(it % STAGES) * STG_BYTES / 2);
        const unsigned* Bs = As + MAT_BYTES / 4;

        #pragma unroll
        for (int ks = 0; ks < 2; ++ks) {             // two k16 steps per BK=32
            const int kw = ks * 8;                   // k offset in words
            unsigned af[4][4], bf[4][2];
            #pragma unroll
            for (int i = 0; i < 4; ++i) {
                const int m = wm + i * 16;
                af[i][0] = As[(m + lq)     * 20 + kw + lr];
                af[i][1] = As[(m + 8 + lq) * 20 + kw + lr];
                af[i][2] = As[(m + lq)     * 20 + kw + 4 + lr];
                af[i][3] = As[(m + 8 + lq) * 20 + kw + 4 + lr];
            }
            #pragma unroll
            for (int j = 0; j < 4; ++j) {
                const int n = wn + j * 8;
                bf[j][0] = Bs[(n + lq) * 20 + kw + lr];
                bf[j][1] = Bs[(n + lq) * 20 + kw + 4 + lr];
            }
            #pragma unroll
            for (int i = 0; i < 4; ++i)
                #pragma unroll
                for (int j = 0; j < 4; ++j)
                    mma16(acc[i][j], af[i], bf[j]);
        }
    }
    __syncthreads();   // all warps done with smem before epilogue reuses it

    // ------------------------------- epilogue -------------------------------
    if (MODE == 0) {
        __half* C = (__half*)Cg;
        #pragma unroll
        for (int i = 0; i < 4; ++i) {
            const int r = row0 + wm + i * 16 + lq;
            #pragma unroll
            for (int j = 0; j < 4; ++j) {
                const int c = col0 + wn + j * 8 + 2 * lr;
                const float b0 = bias[c], b1 = bias[c + 1];
                *(__half2*)&C[(size_t)r * DM + c] =
                    __float22half2_rn(make_float2(acc[i][j][0] + b0, acc[i][j][1] + b1));
                *(__half2*)&C[(size_t)(r + 8) * DM + c] =
                    __float22half2_rn(make_float2(acc[i][j][2] + b0, acc[i][j][3] + b1));
            }
        }
    } else if (MODE == 1) {
        float* C = (float*)Cg + (size_t)blockIdx.z * SEQ * SEQ;
        const float scale = 1.0f / 32.0f;
        #pragma unroll
        for (int i = 0; i < 4; ++i) {
            const int r = row0 + wm + i * 16 + lq;
            #pragma unroll
            for (int j = 0; j < 4; ++j) {
                const int c = col0 + wn + j * 8 + 2 * lr;
                *(float2*)&C[(size_t)r * SEQ + c] =
                    make_float2(acc[i][j][0] * scale, acc[i][j][1] * scale);
                *(float2*)&C[(size_t)(r + 8) * SEQ + c] =
                    make_float2(acc[i][j][2] * scale, acc[i][j][3] * scale);
            }
        }
    } else if (MODE == 2) {
        float* C = (float*)Cg + (size_t)blockIdx.z * SEQ * DM;
        #pragma unroll
        for (int i = 0; i < 4; ++i) {
            const int r = row0 + wm + i * 16 + lq;
            #pragma unroll
            for (int j = 0; j < 4; ++j) {
                const int c = col0 + wn + j * 8 + 2 * lr;
                *(float2*)&C[(size_t)r * DM + c] = make_float2(acc[i][j][0], acc[i][j][1]);
                *(float2*)&C[(size_t)(r + 8) * DM + c] = make_float2(acc[i][j][2], acc[i][j][3]);
            }
        }
    } else {
        // MODE 3: transposed store through per-warp smem staging (32n x 64m, pad 72)
        const int wid = tid >> 5;
        __half* ts = smem_h + (size_t)wid * 32 * 72;
        #pragma unroll
        for (int i = 0; i < 4; ++i) {
            const int ml = i * 16 + lq;
            #pragma unroll
            for (int j = 0; j < 4; ++j) {
                const int nl = j * 8 + 2 * lr;
                const int c = col0 + wn + nl;
                const float b0 = bias[c], b1 = bias[c + 1];
                ts[nl * 72 + ml]           = __float2half_rn(acc[i][j][0] + b0);
                ts[(nl + 1) * 72 + ml]     = __float2half_rn(acc[i][j][1] + b1);
                ts[nl * 72 + ml + 8]       = __float2half_rn(acc[i][j][2] + b0);
                ts[(nl + 1) * 72 + ml + 8] = __float2half_rn(acc[i][j][3] + b1);
            }
        }
        __syncwarp();
        __half* vtb = (__half*)Cg + (size_t)(row0 >> 11) * DM * SEQ;
        const int s0 = (row0 & (SEQ - 1)) + wm;
        const int n = col0 + wn + lane;
        #pragma unroll
        for (int i8 = 0; i8 < 8; ++i8) {
            uint4 v = *(uint4*)&ts[lane * 72 + i8 * 8];
            *(uint4*)&vtb[(size_t)n * SEQ + s0 + i8 * 8] = v;
        }
    }
}

// ---------------------------------------------------------------------------
// Online softmax: fp32 scores in, fp16 probs out (zeroed masked tail).
// ---------------------------------------------------------------------------
__global__ __launch_bounds__(256) void softmax_kernel(
    const float* __restrict__ S, __half* __restrict__ P)
{
    __shared__ float redm[8], reds[8];
    const int r = blockIdx.x;
    const int qi = r & (SEQ - 1);
    const float* row = S + (size_t)r * SEQ;
    __half* prow = P + (size_t)r * SEQ;
    const int L = qi + 1;
    const int L4 = L >> 2;
    const float4* row4 = (const float4*)row;
    const int tid = threadIdx.x;
    const int wid = tid >> 5, lane = tid & 31;

    float m = -FLT_MAX, s = 0.0f;
    for (int j = tid; j < L4; j += 256) {
        float4 v = row4[j];
        float cm = fmaxf(fmaxf(v.x, v.y), fmaxf(v.z, v.w));
        float nm = fmaxf(m, cm);
        s = s * __expf(m - nm)
          + __expf(v.x - nm) + __expf(v.y - nm) + __expf(v.z - nm) + __expf(v.w - nm);
        m = nm;
    }
    for (int j = L4 * 4 + tid; j < L; j += 256) {
        float v = row[j];
        float nm = fmaxf(m, v);
        s = s * __expf(m - nm) + __expf(v - nm);
        m = nm;
    }
    #pragma unroll
    for (int o = 16; o; o >>= 1) {
        float m2 = __shfl_xor_sync(0xffffffffu, m, o);
        float s2 = __shfl_xor_sync(0xffffffffu, s, o);
        float nm = fmaxf(m, m2);
        s = s * __expf(m - nm) + s2 * __expf(m2 - nm);
        m = nm;
    }
    if (lane == 0) { redm[wid] = m; reds[wid] = s; }
    __syncthreads();
    float M = -FLT_MAX;
    #pragma unroll
    for (int w = 0; w < 8; ++w) M = fmaxf(M, redm[w]);
    float Stot = 0.0f;
    #pragma unroll
    for (int w = 0; w < 8; ++w) Stot += reds[w] * __expf(redm[w] - M);
    const float inv = 1.0f / Stot;

    for (int j = tid; j < L4; j += 256) {
        float4 v = row4[j];
        __half2 h0 = __float22half2_rn(make_float2(__expf(v.x - M) * inv, __expf(v.y - M) * inv));
        __half2 h1 = __float22half2_rn(make_float2(__expf(v.z - M) * inv, __expf(v.w - M) * inv));
        ((__half2*)prow)[2 * j]     = h0;
        ((__half2*)prow)[2 * j + 1] = h1;
    }
    for (int j = L4 * 4 + tid; j < L; j += 256)
        prow[j] = __float2half_rn(__expf(row[j] - M) * inv);
    for (int j = L + tid; j < SEQ; j += 256) prow[j] = __float2half_rn(0.0f);
}

// ---------------------------------------------------------------------------
extern "C" void kernel_launch(void* const* d_in, const int* in_sizes, int n_in,
                              void* d_out, int out_size)
{
    (void)in_sizes; (void)n_in; (void)out_size;
    const float* x  = (const float*)d_in[0];
    const float* Wq = (const float*)d_in[1];
    const float* bq = (const float*)d_in[2];
    const float* Wk = (const float*)d_in[3];
    const float* bk = (const float*)d_in[4];
    const float* Wv = (const float*)d_in[5];
    const float* bv = (const float*)d_in[6];
    float* out = (float*)d_out;

    __half *xh, *wq, *wk, *wv, *qh, *kh, *vt, *p;
    float *s;
    cudaGetSymbolAddress((void**)&xh, g_xh);
    cudaGetSymbolAddress((void**)&wq, g_wq);
    cudaGetSymbolAddress((void**)&wk, g_wk);
    cudaGetSymbolAddress((void**)&wv, g_wv);
    cudaGetSymbolAddress((void**)&qh, g_qh);
    cudaGetSymbolAddress((void**)&kh, g_kh);
    cudaGetSymbolAddress((void**)&vt, g_vt);
    cudaGetSymbolAddress((void**)&p,  g_p);
    cudaGetSymbolAddress((void**)&s,  g_s);

    cudaFuncSetAttribute(mm_h<0>, cudaFuncAttributeMaxDynamicSharedMemorySize, SMEM_BYTES);
    cudaFuncSetAttribute(mm_h<1>, cudaFuncAttributeMaxDynamicSharedMemorySize, SMEM_BYTES);
    cudaFuncSetAttribute(mm_h<2>, cudaFuncAttributeMaxDynamicSharedMemorySize, SMEM_BYTES);
    cudaFuncSetAttribute(mm_h<3>, cudaFuncAttributeMaxDynamicSharedMemorySize, SMEM_BYTES);

    dim3 blk(256);

    const int nX4 = ROWS * DM / 4, nW4 = DM * DM / 4;
    cvt_f2h<<<(nX4 + 255) / 256, blk>>>(x,  xh, nX4);
    cvt_f2h<<<(nW4 + 255) / 256, blk>>>(Wq, wq, nW4);
    cvt_f2h<<<(nW4 + 255) / 256, blk>>>(Wk, wk, nW4);
    cvt_f2h<<<(nW4 + 255) / 256, blk>>>(Wv, wv, nW4);

    // QKV projections (V written transposed)
    dim3 gProj(DM / BN, ROWS / BM);              // (8, 64)
    mm_h<0><<<gProj, blk, SMEM_BYTES>>>(xh, wq, bq, qh);
    mm_h<0><<<gProj, blk, SMEM_BYTES>>>(xh, wk, bk, kh);
    mm_h<3><<<gProj, blk, SMEM_BYTES>>>(xh, wv, bv, vt);

    // Causal scores (fp32 out)
    dim3 gScores(SEQ / BN, SEQ / BM, BATCH);     // (16, 16, 4)
    mm_h<1><<<gScores, blk, SMEM_BYTES>>>(qh, kh, nullptr, s);

    // Row softmax (fp32 -> fp16 probs)
    softmax_kernel<<<ROWS, blk>>>(s, p);

    // O = P Vt^T (fp32 out)
    dim3 gPV(DM / BN, SEQ / BM, BATCH);          // (8, 16, 4)
    mm_h<2><<<gPV, blk, SMEM_BYTES>>>(p, vt, nullptr, out);
}

// round 8
// speedup vs baseline: 7.0240x; 1.1360x over previous
#include <cuda_runtime.h>
#include <cuda_fp16.h>
#include <math.h>
#include <float.h>
#include <stdint.h>

#define BATCH 4
#define SEQ   2048
#define DM    1024
#define ROWS  (BATCH * SEQ)   // 8192

#define BM 128
#define BN 128
#define BK 32                 // halves per K-slice
#define LDH 40                // halves per smem row (80B; 16B-aligned, LDSM conflict-free)
#define STAGES 3
#define MAT_BYTES (128 * LDH * 2)            // 10240 per matrix tile
#define STG_BYTES (2 * MAT_BYTES)            // 20480
#define SMEM_BYTES (STAGES * STG_BYTES)      // 61440

// Scratch (allocation-free rule: __device__ globals)
__device__ __half g_xh[(size_t)ROWS * DM];
__device__ __half g_wq[(size_t)DM * DM];
__device__ __half g_wk[(size_t)DM * DM];
__device__ __half g_wv[(size_t)DM * DM];
__device__ __half g_qh[(size_t)ROWS * DM];
__device__ __half g_kh[(size_t)ROWS * DM];
__device__ __half g_vt[(size_t)BATCH * DM * SEQ];  // V transposed per batch
__device__ float  g_s [(size_t)BATCH * SEQ * SEQ]; // fp32 scores
__device__ __half g_p [(size_t)BATCH * SEQ * SEQ]; // fp16 probs

__device__ __forceinline__ void mma16(float c[4], const unsigned a[4], const unsigned b[2]) {
    asm volatile(
        "mma.sync.aligned.m16n8k16.row.col.f32.f16.f16.f32 "
        "{%0,%1,%2,%3},{%4,%5,%6,%7},{%8,%9},{%0,%1,%2,%3};"
        : "+f"(c[0]), "+f"(c[1]), "+f"(c[2]), "+f"(c[3])
        : "r"(a[0]), "r"(a[1]), "r"(a[2]), "r"(a[3]), "r"(b[0]), "r"(b[1]));
}

__device__ __forceinline__ void ldsm_x4(unsigned r[4], unsigned addr) {
    asm volatile("ldmatrix.sync.aligned.m8n8.x4.shared.b16 {%0,%1,%2,%3}, [%4];"
        : "=r"(r[0]), "=r"(r[1]), "=r"(r[2]), "=r"(r[3]) : "r"(addr));
}

__device__ __forceinline__ void cp16(unsigned smem_u32, const void* gptr) {
    asm volatile("cp.async.cg.shared.global [%0], [%1], 16;\n" :: "r"(smem_u32), "l"(gptr));
}
__device__ __forceinline__ void cp_commit() { asm volatile("cp.async.commit_group;\n"); }
template<int N>
__device__ __forceinline__ void cp_wait() { asm volatile("cp.async.wait_group %0;\n" :: "n"(N)); }

// ---------------------------------------------------------------------------
// fp32 -> fp16 conversion (RN)
// ---------------------------------------------------------------------------
__global__ void cvt_f2h(const float* __restrict__ in, __half* __restrict__ out, int n4)
{
    int i = blockIdx.x * blockDim.x + threadIdx.x;
    if (i >= n4) return;
    float4 v = ((const float4*)in)[i];
    ((__half2*)out)[2 * i]     = __float22half2_rn(make_float2(v.x, v.y));
    ((__half2*)out)[2 * i + 1] = __float22half2_rn(make_float2(v.z, v.w));
}

// ---------------------------------------------------------------------------
// fp16 m16n8k16 GEMM, 128x128 tile, cp.async 3-stage, LDSM fragment loads.
// MODE 0: Ch = (A W^T + bias)           half out      (Q/K projections)
// MODE 3: Vt = (A W^T + bias)^T         half out      (V projection, transposed)
// MODE 1: S[b] = (Q K^T)/32             fp32 out, skip above-diag tiles
// MODE 2: O[b] = P Vt^T                 fp32 out, K limited by causality
// ---------------------------------------------------------------------------
template<int MODE>
__global__ __launch_bounds__(256, 2) void mm_h(
    const __half* __restrict__ Ag, const __half* __restrict__ Bg,
    const float* __restrict__ bias, void* __restrict__ Cg)
{
    const int row0 = blockIdx.y * BM;
    const int col0 = blockIdx.x * BN;
    const __half* A = Ag;
    const __half* B = Bg;
    int ldA = DM, ldB = DM;
    if (MODE == 1) {
        if (col0 > row0) return;     // fully masked tile, never read downstream
        size_t off = (size_t)blockIdx.z * SEQ * DM;
        A += off; B += off;
    }
    if (MODE == 2) {
        A += (size_t)blockIdx.z * SEQ * SEQ;
        B += (size_t)blockIdx.z * DM * SEQ;
        ldA = SEQ; ldB = SEQ;
    }
    const int kEnd  = (MODE == 2) ? (row0 + BM) : DM;
    const int nIter = kEnd / BK;

    extern __shared__ __align__(16) __half smem_h[];
    const unsigned smem_base = (unsigned)__cvta_generic_to_shared(smem_h);

    const int tid = threadIdx.x;
    auto issue = [&](int it) {
        const int k0 = it * BK;
        const unsigned sa = smem_base + (it % STAGES) * STG_BYTES;
        const unsigned sb = sa + MAT_BYTES;
        #pragma unroll
        for (int t = 0; t < 2; ++t) {
            int cid = tid + t * 256;
            int r = cid >> 2, c8 = (cid & 3) * 8;
            cp16(sa + (r * LDH + c8) * 2, A + (size_t)(row0 + r) * ldA + k0 + c8);
        }
        #pragma unroll
        for (int t = 0; t < 2; ++t) {
            int cid = tid + t * 256;
            int r = cid >> 2, c8 = (cid & 3) * 8;
            cp16(sb + (r * LDH + c8) * 2, B + (size_t)(col0 + r) * ldB + k0 + c8);
        }
    };

    const int lane = tid & 31;
    const int wm = (tid >> 7) * 64;          // warp rows
    const int wn = ((tid >> 5) & 3) * 32;    // warp cols
    const int lq = lane >> 2, lr = lane & 3;

    // LDSM lane address components (halves)
    const int lr8 = lane & 7;
    // A x4: regs = [rows0-7 k0-7, rows8-15 k0-7, rows0-7 k8-15, rows8-15 k8-15]
    const unsigned aoff = (unsigned)(((wm + lr8 + ((lane >> 3) & 1) * 8) * LDH
                                      + ((lane >> 4) & 1) * 8) * 2);
    // B x4: regs = [n0-7 k0-7, n0-7 k8-15, n8-15 k0-7, n8-15 k8-15]
    const unsigned boff = (unsigned)(((wn + lr8 + ((lane >> 4) & 1) * 8) * LDH
                                      + ((lane >> 3) & 1) * 8) * 2);

    float acc[4][4][4] = {};

    #pragma unroll
    for (int s = 0; s < STAGES - 1; ++s) {
        if (s < nIter) issue(s);
        cp_commit();
    }

    for (int it = 0; it < nIter; ++it) {
        cp_wait<STAGES - 2>();
        __syncthreads();

        if (it + STAGES - 1 < nIter) issue(it + STAGES - 1);
        cp_commit();

        const unsigned sA = smem_base + (it % STAGES) * STG_BYTES;
        const unsigned sB = sA + MAT_BYTES;

        #pragma unroll
        for (int ks = 0; ks < 2; ++ks) {             // two k16 steps per BK=32
            unsigned af[4][4], bf[4][2];
            #pragma unroll
            for (int i = 0; i < 4; ++i)
                ldsm_x4(af[i], sA + aoff + (unsigned)((i * 16 * LDH + ks * 16) * 2));
            #pragma unroll
            for (int j2 = 0; j2 < 2; ++j2) {
                unsigned bb[4];
                ldsm_x4(bb, sB + boff + (unsigned)((j2 * 16 * LDH + ks * 16) * 2));
                bf[2 * j2][0] = bb[0]; bf[2 * j2][1] = bb[1];
                bf[2 * j2 + 1][0] = bb[2]; bf[2 * j2 + 1][1] = bb[3];
            }
            #pragma unroll
            for (int i = 0; i < 4; ++i)
                #pragma unroll
                for (int j = 0; j < 4; ++j)
                    mma16(acc[i][j], af[i], bf[j]);
        }
    }
    __syncthreads();   // all warps done with smem before epilogue reuses it

    // ------------------------------- epilogue -------------------------------
    if (MODE == 0) {
        __half* C = (__half*)Cg;
        #pragma unroll
        for (int i = 0; i < 4; ++i) {
            const int r = row0 + wm + i * 16 + lq;
            #pragma unroll
            for (int j = 0; j < 4; ++j) {
                const int c = col0 + wn + j * 8 + 2 * lr;
                const float b0 = bias[c], b1 = bias[c + 1];
                *(__half2*)&C[(size_t)r * DM + c] =
                    __float22half2_rn(make_float2(acc[i][j][0] + b0, acc[i][j][1] + b1));
                *(__half2*)&C[(size_t)(r + 8) * DM + c] =
                    __float22half2_rn(make_float2(acc[i][j][2] + b0, acc[i][j][3] + b1));
            }
        }
    } else if (MODE == 1) {
        float* C = (float*)Cg + (size_t)blockIdx.z * SEQ * SEQ;
        const float scale = 1.0f / 32.0f;
        #pragma unroll
        for (int i = 0; i < 4; ++i) {
            const int r = row0 + wm + i * 16 + lq;
            #pragma unroll
            for (int j = 0; j < 4; ++j) {
                const int c = col0 + wn + j * 8 + 2 * lr;
                *(float2*)&C[(size_t)r * SEQ + c] =
                    make_float2(acc[i][j][0] * scale, acc[i][j][1] * scale);
                *(float2*)&C[(size_t)(r + 8) * SEQ + c] =
                    make_float2(acc[i][j][2] * scale, acc[i][j][3] * scale);
            }
        }
    } else if (MODE == 2) {
        float* C = (float*)Cg + (size_t)blockIdx.z * SEQ * DM;
        #pragma unroll
        for (int i = 0; i < 4; ++i) {
            const int r = row0 + wm + i * 16 + lq;
            #pragma unroll
            for (int j = 0; j < 4; ++j) {
                const int c = col0 + wn + j * 8 + 2 * lr;
                *(float2*)&C[(size_t)r * DM + c] = make_float2(acc[i][j][0], acc[i][j][1]);
                *(float2*)&C[(size_t)(r + 8) * DM + c] = make_float2(acc[i][j][2], acc[i][j][3]);
            }
        }
    } else {
        // MODE 3: transposed store through per-warp smem staging (32n x 64m, pad 72)
        const int wid = tid >> 5;
        __half* ts = smem_h + (size_t)wid * 32 * 72;
        #pragma unroll
        for (int i = 0; i < 4; ++i) {
            const int ml = i * 16 + lq;
            #pragma unroll
            for (int j = 0; j < 4; ++j) {
                const int nl = j * 8 + 2 * lr;
                const int c = col0 + wn + nl;
                const float b0 = bias[c], b1 = bias[c + 1];
                ts[nl * 72 + ml]           = __float2half_rn(acc[i][j][0] + b0);
                ts[(nl + 1) * 72 + ml]     = __float2half_rn(acc[i][j][1] + b1);
                ts[nl * 72 + ml + 8]       = __float2half_rn(acc[i][j][2] + b0);
                ts[(nl + 1) * 72 + ml + 8] = __float2half_rn(acc[i][j][3] + b1);
            }
        }
        __syncwarp();
        __half* vtb = (__half*)Cg + (size_t)(row0 >> 11) * DM * SEQ;
        const int s0 = (row0 & (SEQ - 1)) + wm;
        const int n = col0 + wn + lane;
        #pragma unroll
        for (int i8 = 0; i8 < 8; ++i8) {
            uint4 v = *(uint4*)&ts[lane * 72 + i8 * 8];
            *(uint4*)&vtb[(size_t)n * SEQ + s0 + i8 * 8] = v;
        }
    }
}

// ---------------------------------------------------------------------------
// Online softmax: fp32 scores in, fp16 probs out (zeroed masked tail).
// ---------------------------------------------------------------------------
__global__ __launch_bounds__(256) void softmax_kernel(
    const float* __restrict__ S, __half* __restrict__ P)
{
    __shared__ float redm[8], reds[8];
    const int r = blockIdx.x;
    const int qi = r & (SEQ - 1);
    const float* row = S + (size_t)r * SEQ;
    __half* prow = P + (size_t)r * SEQ;
    const int L = qi + 1;
    const int L4 = L >> 2;
    const float4* row4 = (const float4*)row;
    const int tid = threadIdx.x;
    const int wid = tid >> 5, lane = tid & 31;

    float m = -FLT_MAX, s = 0.0f;
    for (int j = tid; j < L4; j += 256) {
        float4 v = row4[j];
        float cm = fmaxf(fmaxf(v.x, v.y), fmaxf(v.z, v.w));
        float nm = fmaxf(m, cm);
        s = s * __expf(m - nm)
          + __expf(v.x - nm) + __expf(v.y - nm) + __expf(v.z - nm) + __expf(v.w - nm);
        m = nm;
    }
    for (int j = L4 * 4 + tid; j < L; j += 256) {
        float v = row[j];
        float nm = fmaxf(m, v);
        s = s * __expf(m - nm) + __expf(v - nm);
        m = nm;
    }
    #pragma unroll
    for (int o = 16; o; o >>= 1) {
        float m2 = __shfl_xor_sync(0xffffffffu, m, o);
        float s2 = __shfl_xor_sync(0xffffffffu, s, o);
        float nm = fmaxf(m, m2);
        s = s * __expf(m - nm) + s2 * __expf(m2 - nm);
        m = nm;
    }
    if (lane == 0) { redm[wid] = m; reds[wid] = s; }
    __syncthreads();
    float M = -FLT_MAX;
    #pragma unroll
    for (int w = 0; w < 8; ++w) M = fmaxf(M, redm[w]);
    float Stot = 0.0f;
    #pragma unroll
    for (int w = 0; w < 8; ++w) Stot += reds[w] * __expf(redm[w] - M);
    const float inv = 1.0f / Stot;

    for (int j = tid; j < L4; j += 256) {
        float4 v = row4[j];
        ((__half2*)prow)[2 * j] =
            __float22half2_rn(make_float2(__expf(v.x - M) * inv, __expf(v.y - M) * inv));
        ((__half2*)prow)[2 * j + 1] =
            __float22half2_rn(make_float2(__expf(v.z - M) * inv, __expf(v.w - M) * inv));
    }
    for (int j = L4 * 4 + tid; j < L; j += 256)
        prow[j] = __float2half_rn(__expf(row[j] - M) * inv);
    for (int j = L + tid; j < SEQ; j += 256) prow[j] = __float2half_rn(0.0f);
}

// ---------------------------------------------------------------------------
extern "C" void kernel_launch(void* const* d_in, const int* in_sizes, int n_in,
                              void* d_out, int out_size)
{
    (void)in_sizes; (void)n_in; (void)out_size;
    const float* x  = (const float*)d_in[0];
    const float* Wq = (const float*)d_in[1];
    const float* bq = (const float*)d_in[2];
    const float* Wk = (const float*)d_in[3];
    const float* bk = (const float*)d_in[4];
    const float* Wv = (const float*)d_in[5];
    const float* bv = (const float*)d_in[6];
    float* out = (float*)d_out;

    __half *xh, *wq, *wk, *wv, *qh, *kh, *vt, *p;
    float *s;
    cudaGetSymbolAddress((void**)&xh, g_xh);
    cudaGetSymbolAddress((void**)&wq, g_wq);
    cudaGetSymbolAddress((void**)&wk, g_wk);
    cudaGetSymbolAddress((void**)&wv, g_wv);
    cudaGetSymbolAddress((void**)&qh, g_qh);
    cudaGetSymbolAddress((void**)&kh, g_kh);
    cudaGetSymbolAddress((void**)&vt, g_vt);
    cudaGetSymbolAddress((void**)&p,  g_p);
    cudaGetSymbolAddress((void**)&s,  g_s);

    cudaFuncSetAttribute(mm_h<0>, cudaFuncAttributeMaxDynamicSharedMemorySize, SMEM_BYTES);
    cudaFuncSetAttribute(mm_h<1>, cudaFuncAttributeMaxDynamicSharedMemorySize, SMEM_BYTES);
    cudaFuncSetAttribute(mm_h<2>, cudaFuncAttributeMaxDynamicSharedMemorySize, SMEM_BYTES);
    cudaFuncSetAttribute(mm_h<3>, cudaFuncAttributeMaxDynamicSharedMemorySize, SMEM_BYTES);

    dim3 blk(256);

    const int nX4 = ROWS * DM / 4, nW4 = DM * DM / 4;
    cvt_f2h<<<(nX4 + 255) / 256, blk>>>(x,  xh, nX4);
    cvt_f2h<<<(nW4 + 255) / 256, blk>>>(Wq, wq, nW4);
    cvt_f2h<<<(nW4 + 255) / 256, blk>>>(Wk, wk, nW4);
    cvt_f2h<<<(nW4 + 255) / 256, blk>>>(Wv, wv, nW4);

    // QKV projections (V written transposed)
    dim3 gProj(DM / BN, ROWS / BM);              // (8, 64)
    mm_h<0><<<gProj, blk, SMEM_BYTES>>>(xh, wq, bq, qh);
    mm_h<0><<<gProj, blk, SMEM_BYTES>>>(xh, wk, bk, kh);
    mm_h<3><<<gProj, blk, SMEM_BYTES>>>(xh, wv, bv, vt);

    // Causal scores (fp32 out)
    dim3 gScores(SEQ / BN, SEQ / BM, BATCH);     // (16, 16, 4)
    mm_h<1><<<gScores, blk, SMEM_BYTES>>>(qh, kh, nullptr, s);

    // Row softmax (fp32 -> fp16 probs)
    softmax_kernel<<<ROWS, blk>>>(s, p);

    // O = P Vt^T (fp32 out)
    dim3 gPV(DM / BN, SEQ / BM, BATCH);          // (8, 16, 4)
    mm_h<2><<<gPV, blk, SMEM_BYTES>>>(p, vt, nullptr, out);
}

// round 9
// speedup vs baseline: 7.5011x; 1.0679x over previous
#include <cuda_runtime.h>
#include <cuda_fp16.h>
#include <math.h>
#include <float.h>
#include <stdint.h>

#define BATCH 4
#define SEQ   2048
#define DM    1024
#define ROWS  (BATCH * SEQ)   // 8192

#define BM 128
#define BN 128
#define BK 32                 // halves per K-slice
#define LDH 40                // halves per smem row (80B; LDSM conflict-free)
#define THREADS 128
#define STAGES 3
#define MAT_BYTES (128 * LDH * 2)            // 10240 per matrix tile
#define STG_BYTES (2 * MAT_BYTES)            // 20480
#define SMEM_BYTES (STAGES * STG_BYTES)      // 61440

// Scratch (allocation-free rule: __device__ globals)
__device__ __half g_xh[(size_t)ROWS * DM];
__device__ __half g_wq[(size_t)DM * DM];
__device__ __half g_wk[(size_t)DM * DM];
__device__ __half g_wv[(size_t)DM * DM];
__device__ __half g_qh[(size_t)ROWS * DM];
__device__ __half g_kh[(size_t)ROWS * DM];
__device__ __half g_vt[(size_t)BATCH * DM * SEQ];  // V transposed per batch
__device__ float  g_s [(size_t)BATCH * SEQ * SEQ]; // fp32 scores
__device__ __half g_p [(size_t)BATCH * SEQ * SEQ]; // fp16 probs

__device__ __forceinline__ void mma16(float c[4], const unsigned a[4], const unsigned b[2]) {
    asm volatile(
        "mma.sync.aligned.m16n8k16.row.col.f32.f16.f16.f32 "
        "{%0,%1,%2,%3},{%4,%5,%6,%7},{%8,%9},{%0,%1,%2,%3};"
        : "+f"(c[0]), "+f"(c[1]), "+f"(c[2]), "+f"(c[3])
        : "r"(a[0]), "r"(a[1]), "r"(a[2]), "r"(a[3]), "r"(b[0]), "r"(b[1]));
}

__device__ __forceinline__ void ldsm_x4(unsigned r[4], unsigned addr) {
    asm volatile("ldmatrix.sync.aligned.m8n8.x4.shared.b16 {%0,%1,%2,%3}, [%4];"
        : "=r"(r[0]), "=r"(r[1]), "=r"(r[2]), "=r"(r[3]) : "r"(addr));
}

__device__ __forceinline__ void cp16(unsigned smem_u32, const void* gptr) {
    asm volatile("cp.async.cg.shared.global [%0], [%1], 16;\n" :: "r"(smem_u32), "l"(gptr));
}
__device__ __forceinline__ void cp_commit() { asm volatile("cp.async.commit_group;\n"); }
template<int N>
__device__ __forceinline__ void cp_wait() { asm volatile("cp.async.wait_group %0;\n" :: "n"(N)); }

// ---------------------------------------------------------------------------
// fp32 -> fp16 conversion (RN)
// ---------------------------------------------------------------------------
__global__ void cvt_f2h(const float* __restrict__ in, __half* __restrict__ out, int n4)
{
    int i = blockIdx.x * blockDim.x + threadIdx.x;
    if (i >= n4) return;
    float4 v = ((const float4*)in)[i];
    ((__half2*)out)[2 * i]     = __float22half2_rn(make_float2(v.x, v.y));
    ((__half2*)out)[2 * i + 1] = __float22half2_rn(make_float2(v.z, v.w));
}

// ---------------------------------------------------------------------------
// fp16 m16n8k16 GEMM, 128x128 CTA tile, 4 warps x (64x64), cp.async 3-stage.
// MODE 0: Ch = (A W^T + bias)           half out      (Q/K projections)
// MODE 3: Vt = (A W^T + bias)^T         half out      (V projection, transposed)
// MODE 1: S[b] = (Q K^T)/32             fp32 out, skip above-diag tiles
// MODE 2: O[b] = P Vt^T                 fp32 out, K limited by causality
// ---------------------------------------------------------------------------
template<int MODE>
__global__ __launch_bounds__(THREADS, 2) void mm_h(
    const __half* __restrict__ Ag, const __half* __restrict__ Bg,
    const float* __restrict__ bias, void* __restrict__ Cg)
{
    const int row0 = blockIdx.y * BM;
    const int col0 = blockIdx.x * BN;
    const __half* A = Ag;
    const __half* B = Bg;
    int ldA = DM, ldB = DM;
    if (MODE == 1) {
        if (col0 > row0) return;     // fully masked tile, never read downstream
        size_t off = (size_t)blockIdx.z * SEQ * DM;
        A += off; B += off;
    }
    if (MODE == 2) {
        A += (size_t)blockIdx.z * SEQ * SEQ;
        B += (size_t)blockIdx.z * DM * SEQ;
        ldA = SEQ; ldB = SEQ;
    }
    const int kEnd  = (MODE == 2) ? (row0 + BM) : DM;
    const int nIter = kEnd / BK;

    extern __shared__ __align__(16) __half smem_h[];
    const unsigned smem_base = (unsigned)__cvta_generic_to_shared(smem_h);

    const int tid = threadIdx.x;
    // cp.async: A tile 128x32 halves = 512 x 16B chunks; same for B; 4 each/thread
    auto issue = [&](int it) {
        const int k0 = it * BK;
        const unsigned sa = smem_base + (it % STAGES) * STG_BYTES;
        const unsigned sb = sa + MAT_BYTES;
        #pragma unroll
        for (int t = 0; t < 4; ++t) {
            int cid = tid + t * THREADS;
            int r = cid >> 2, c8 = (cid & 3) * 8;
            cp16(sa + (r * LDH + c8) * 2, A + (size_t)(row0 + r) * ldA + k0 + c8);
        }
        #pragma unroll
        for (int t = 0; t < 4; ++t) {
            int cid = tid + t * THREADS;
            int r = cid >> 2, c8 = (cid & 3) * 8;
            cp16(sb + (r * LDH + c8) * 2, B + (size_t)(col0 + r) * ldB + k0 + c8);
        }
    };

    const int lane = tid & 31;
    const int wid = tid >> 5;
    const int wm = (wid >> 1) * 64;          // warp rows (2x2 warp grid)
    const int wn = (wid & 1) * 64;           // warp cols
    const int lq = lane >> 2, lr = lane & 3;

    // LDSM lane address components (halves)
    const int lr8 = lane & 7;
    // A x4: [rows0-7 k0-7, rows8-15 k0-7, rows0-7 k8-15, rows8-15 k8-15]
    const unsigned aoff = (unsigned)(((wm + lr8 + ((lane >> 3) & 1) * 8) * LDH
                                      + ((lane >> 4) & 1) * 8) * 2);
    // B x4: [n0-7 k0-7, n0-7 k8-15, n8-15 k0-7, n8-15 k8-15]
    const unsigned boff = (unsigned)(((wn + lr8 + ((lane >> 4) & 1) * 8) * LDH
                                      + ((lane >> 3) & 1) * 8) * 2);

    float acc[4][8][4] = {};   // 4 m-tiles x 8 n-tiles x 4 regs = 64x64 per warp

    #pragma unroll
    for (int s = 0; s < STAGES - 1; ++s) {
        if (s < nIter) issue(s);
        cp_commit();
    }

    for (int it = 0; it < nIter; ++it) {
        cp_wait<STAGES - 2>();
        __syncthreads();

        if (it + STAGES - 1 < nIter) issue(it + STAGES - 1);
        cp_commit();

        const unsigned sA = smem_base + (it % STAGES) * STG_BYTES;
        const unsigned sB = sA + MAT_BYTES;

        #pragma unroll
        for (int ks = 0; ks < 2; ++ks) {             // two k16 steps per BK=32
            unsigned af[4][4], bf[8][2];
            #pragma unroll
            for (int i = 0; i < 4; ++i)
                ldsm_x4(af[i], sA + aoff + (unsigned)((i * 16 * LDH + ks * 16) * 2));
            #pragma unroll
            for (int j2 = 0; j2 < 4; ++j2) {
                unsigned bb[4];
                ldsm_x4(bb, sB + boff + (unsigned)((j2 * 16 * LDH + ks * 16) * 2));
                bf[2 * j2][0] = bb[0]; bf[2 * j2][1] = bb[1];
                bf[2 * j2 + 1][0] = bb[2]; bf[2 * j2 + 1][1] = bb[3];
            }
            #pragma unroll
            for (int i = 0; i < 4; ++i)
                #pragma unroll
                for (int j = 0; j < 8; ++j)
                    mma16(acc[i][j], af[i], bf[j]);
        }
    }
    __syncthreads();   // all warps done with smem before epilogue reuses it

    // ------------------------------- epilogue -------------------------------
    if (MODE == 0) {
        __half* C = (__half*)Cg;
        #pragma unroll
        for (int i = 0; i < 4; ++i) {
            const int r = row0 + wm + i * 16 + lq;
            #pragma unroll
            for (int j = 0; j < 8; ++j) {
                const int c = col0 + wn + j * 8 + 2 * lr;
                const float b0 = bias[c], b1 = bias[c + 1];
                *(__half2*)&C[(size_t)r * DM + c] =
                    __float22half2_rn(make_float2(acc[i][j][0] + b0, acc[i][j][1] + b1));
                *(__half2*)&C[(size_t)(r + 8) * DM + c] =
                    __float22half2_rn(make_float2(acc[i][j][2] + b0, acc[i][j][3] + b1));
            }
        }
    } else if (MODE == 1) {
        float* C = (float*)Cg + (size_t)blockIdx.z * SEQ * SEQ;
        const float scale = 1.0f / 32.0f;
        #pragma unroll
        for (int i = 0; i < 4; ++i) {
            const int r = row0 + wm + i * 16 + lq;
            #pragma unroll
            for (int j = 0; j < 8; ++j) {
                const int c = col0 + wn + j * 8 + 2 * lr;
                *(float2*)&C[(size_t)r * SEQ + c] =
                    make_float2(acc[i][j][0] * scale, acc[i][j][1] * scale);
                *(float2*)&C[(size_t)(r + 8) * SEQ + c] =
                    make_float2(acc[i][j][2] * scale, acc[i][j][3] * scale);
            }
        }
    } else if (MODE == 2) {
        float* C = (float*)Cg + (size_t)blockIdx.z * SEQ * DM;
        #pragma unroll
        for (int i = 0; i < 4; ++i) {
            const int r = row0 + wm + i * 16 + lq;
            #pragma unroll
            for (int j = 0; j < 8; ++j) {
                const int c = col0 + wn + j * 8 + 2 * lr;
                *(float2*)&C[(size_t)r * DM + c] = make_float2(acc[i][j][0], acc[i][j][1]);
                *(float2*)&C[(size_t)(r + 8) * DM + c] = make_float2(acc[i][j][2], acc[i][j][3]);
            }
        }
    } else {
        // MODE 3: transposed store via per-warp smem staging (64n x 64m, pad 72)
        __half* ts = smem_h + (size_t)wid * 64 * 72;
        #pragma unroll
        for (int i = 0; i < 4; ++i) {
            const int ml = i * 16 + lq;
            #pragma unroll
            for (int j = 0; j < 8; ++j) {
                const int nl = j * 8 + 2 * lr;
                const int c = col0 + wn + nl;
                const float b0 = bias[c], b1 = bias[c + 1];
                ts[nl * 72 + ml]           = __float2half_rn(acc[i][j][0] + b0);
                ts[(nl + 1) * 72 + ml]     = __float2half_rn(acc[i][j][1] + b1);
                ts[nl * 72 + ml + 8]       = __float2half_rn(acc[i][j][2] + b0);
                ts[(nl + 1) * 72 + ml + 8] = __float2half_rn(acc[i][j][3] + b1);
            }
        }
        __syncwarp();
        __half* vtb = (__half*)Cg + (size_t)(row0 >> 11) * DM * SEQ;
        const int s0 = (row0 & (SEQ - 1)) + wm;
        #pragma unroll
        for (int nr2 = 0; nr2 < 2; ++nr2) {
            const int nr = lane + nr2 * 32;
            const int n = col0 + wn + nr;
            #pragma unroll
            for (int i8 = 0; i8 < 8; ++i8) {
                uint4 v = *(uint4*)&ts[nr * 72 + i8 * 8];
                *(uint4*)&vtb[(size_t)n * SEQ + s0 + i8 * 8] = v;
            }
        }
    }
}

// ---------------------------------------------------------------------------
// Online softmax: fp32 scores in, fp16 probs out (tail zeroed to 128-boundary).
// ---------------------------------------------------------------------------
__global__ __launch_bounds__(256) void softmax_kernel(
    const float* __restrict__ S, __half* __restrict__ P)
{
    __shared__ float redm[8], reds[8];
    const int r = blockIdx.x;
    const int qi = r & (SEQ - 1);
    const float* row = S + (size_t)r * SEQ;
    __half* prow = P + (size_t)r * SEQ;
    const int L = qi + 1;
    const int L4 = L >> 2;
    const float4* row4 = (const float4*)row;
    const int tid = threadIdx.x;
    const int wid = tid >> 5, lane = tid & 31;

    float m = -FLT_MAX, s = 0.0f;
    for (int j = tid; j < L4; j += 256) {
        float4 v = row4[j];
        float cm = fmaxf(fmaxf(v.x, v.y), fmaxf(v.z, v.w));
        float nm = fmaxf(m, cm);
        s = s * __expf(m - nm)
          + __expf(v.x - nm) + __expf(v.y - nm) + __expf(v.z - nm) + __expf(v.w - nm);
        m = nm;
    }
    for (int j = L4 * 4 + tid; j < L; j += 256) {
        float v = row[j];
        float nm = fmaxf(m, v);
        s = s * __expf(m - nm) + __expf(v - nm);
        m = nm;
    }
    #pragma unroll
    for (int o = 16; o; o >>= 1) {
        float m2 = __shfl_xor_sync(0xffffffffu, m, o);
        float s2 = __shfl_xor_sync(0xffffffffu, s, o);
        float nm = fmaxf(m, m2);
        s = s * __expf(m - nm) + s2 * __expf(m2 - nm);
        m = nm;
    }
    if (lane == 0) { redm[wid] = m; reds[wid] = s; }
    __syncthreads();
    float M = -FLT_MAX;
    #pragma unroll
    for (int w = 0; w < 8; ++w) M = fmaxf(M, redm[w]);
    float Stot = 0.0f;
    #pragma unroll
    for (int w = 0; w < 8; ++w) Stot += reds[w] * __expf(redm[w] - M);
    const float inv = 1.0f / Stot;

    for (int j = tid; j < L4; j += 256) {
        float4 v = row4[j];
        ((__half2*)prow)[2 * j] =
            __float22half2_rn(make_float2(__expf(v.x - M) * inv, __expf(v.y - M) * inv));
        ((__half2*)prow)[2 * j + 1] =
            __float22half2_rn(make_float2(__expf(v.z - M) * inv, __expf(v.w - M) * inv));
    }
    for (int j = L4 * 4 + tid; j < L; j += 256)
        prow[j] = __float2half_rn(__expf(row[j] - M) * inv);
    // Zero only up to the 128-boundary PV actually reads (kEnd = row0+128).
    const int zEnd = (qi & ~127) + 128;
    for (int j = L + tid; j < zEnd; j += 256) prow[j] = __float2half_rn(0.0f);
}

// ---------------------------------------------------------------------------
extern "C" void kernel_launch(void* const* d_in, const int* in_sizes, int n_in,
                              void* d_out, int out_size)
{
    (void)in_sizes; (void)n_in; (void)out_size;
    const float* x  = (const float*)d_in[0];
    const float* Wq = (const float*)d_in[1];
    const float* bq = (const float*)d_in[2];
    const float* Wk = (const float*)d_in[3];
    const float* bk = (const float*)d_in[4];
    const float* Wv = (const float*)d_in[5];
    const float* bv = (const float*)d_in[6];
    float* out = (float*)d_out;

    __half *xh, *wq, *wk, *wv, *qh, *kh, *vt, *p;
    float *s;
    cudaGetSymbolAddress((void**)&xh, g_xh);
    cudaGetSymbolAddress((void**)&wq, g_wq);
    cudaGetSymbolAddress((void**)&wk, g_wk);
    cudaGetSymbolAddress((void**)&wv, g_wv);
    cudaGetSymbolAddress((void**)&qh, g_qh);
    cudaGetSymbolAddress((void**)&kh, g_kh);
    cudaGetSymbolAddress((void**)&vt, g_vt);
    cudaGetSymbolAddress((void**)&p,  g_p);
    cudaGetSymbolAddress((void**)&s,  g_s);

    cudaFuncSetAttribute(mm_h<0>, cudaFuncAttributeMaxDynamicSharedMemorySize, SMEM_BYTES);
    cudaFuncSetAttribute(mm_h<1>, cudaFuncAttributeMaxDynamicSharedMemorySize, SMEM_BYTES);
    cudaFuncSetAttribute(mm_h<2>, cudaFuncAttributeMaxDynamicSharedMemorySize, SMEM_BYTES);
    cudaFuncSetAttribute(mm_h<3>, cudaFuncAttributeMaxDynamicSharedMemorySize, SMEM_BYTES);

    dim3 blk(THREADS);

    const int nX4 = ROWS * DM / 4, nW4 = DM * DM / 4;
    cvt_f2h<<<(nX4 + 255) / 256, 256>>>(x,  xh, nX4);
    cvt_f2h<<<(nW4 + 255) / 256, 256>>>(Wq, wq, nW4);
    cvt_f2h<<<(nW4 + 255) / 256, 256>>>(Wk, wk, nW4);
    cvt_f2h<<<(nW4 + 255) / 256, 256>>>(Wv, wv, nW4);

    // QKV projections (V written transposed)
    dim3 gProj(DM / BN, ROWS / BM);              // (8, 64)
    mm_h<0><<<gProj, blk, SMEM_BYTES>>>(xh, wq, bq, qh);
    mm_h<0><<<gProj, blk, SMEM_BYTES>>>(xh, wk, bk, kh);
    mm_h<3><<<gProj, blk, SMEM_BYTES>>>(xh, wv, bv, vt);

    // Causal scores (fp32 out)
    dim3 gScores(SEQ / BN, SEQ / BM, BATCH);     // (16, 16, 4)
    mm_h<1><<<gScores, blk, SMEM_BYTES>>>(qh, kh, nullptr, s);

    // Row softmax (fp32 -> fp16 probs)
    softmax_kernel<<<ROWS, 256>>>(s, p);

    // O = P Vt^T (fp32 out)
    dim3 gPV(DM / BN, SEQ / BM, BATCH);          // (8, 16, 4)
    mm_h<2><<<gPV, blk, SMEM_BYTES>>>(p, vt, nullptr, out);
}